// round 10
// baseline (speedup 1.0000x reference)
#include <cuda_runtime.h>
#include <cuda_bf16.h>

// CRF loss: scaled linear-domain forward scan + lane-parallel gold epilogue.
// 1 warp (=1 block, BAR.SYNC floor 3cyc) per batch element; lane = tag.
// Each lane holds the FULL q vector (16 packed f32x2 regs) + its packed
// exp-transition row: per-step matvec = 16 fma.rn.f32x2, zero shuffles.
// q broadcast via ping-pong smem: 1 STS + BAR + 8 broadcast LDS.128.
// Inner loop is minimal: no gold path (moved to vectorized epilogue), and
// rescaling is a pending power-of-2 factor folded into the next exp(feat)
// (1 FMUL) instead of 16 vector muls. Double-buffered global prefetch.

#define BB 256
#define LL 2048
#define TT 32
#define START_IDX 0
#define STOP_IDX 1

typedef unsigned long long u64;

__device__ __forceinline__ u64 ffma2(u64 a, u64 b, u64 c) {
    u64 d; asm("fma.rn.f32x2 %0, %1, %2, %3;" : "=l"(d) : "l"(a), "l"(b), "l"(c)); return d;
}
__device__ __forceinline__ u64 fadd2(u64 a, u64 b) {
    u64 d; asm("add.rn.f32x2 %0, %1, %2;" : "=l"(d) : "l"(a), "l"(b)); return d;
}
__device__ __forceinline__ u64 pack2(float lo, float hi) {
    return ((u64)__float_as_uint(hi) << 32) | (u64)__float_as_uint(lo);
}
__device__ __forceinline__ float lo2(u64 v) { return __uint_as_float((unsigned)v); }
__device__ __forceinline__ float hi2(u64 v) { return __uint_as_float((unsigned)(v >> 32)); }

__global__ void init_out_kernel(float* __restrict__ out) { *out = 0.0f; }

// issue 8 steps of loads (no consumption here -> latency hidden)
#define LOADG(F, MA, MB4, BASE) do {                                          \
    _Pragma("unroll")                                                         \
    for (int _i = 0; _i < 8; _i++)                                            \
        F[_i] = fb[(size_t)((BASE) + _i) * TT + lane];                        \
    MA  = *(const float4*)(mbp + (BASE));                                     \
    MB4 = *(const float4*)(mbp + (BASE) + 4);                                 \
} while (0)

// process 8 steps from a prefetched buffer (fully branch-free, no gold path)
#define PROC(F, MA, MB4) do {                                                 \
    float mk[8] = {MA.x, MA.y, MA.z, MA.w, MB4.x, MB4.y, MB4.z, MB4.w};       \
    _Pragma("unroll")                                                         \
    for (int i = 0; i < 8; i++) {                                             \
        float efp = __expf(F[i]) * pend;  /* pending rescale folded here */   \
        u64 a0 = 0ull, a1 = 0ull, a2 = 0ull, a3 = 0ull;                       \
        _Pragma("unroll")                                                     \
        for (int j = 0; j < 16; j += 4) { /* chains spread over LDS order */  \
            a0 = ffma2(qp[j + 0], Erp[j + 0], a0);                            \
            a1 = ffma2(qp[j + 1], Erp[j + 1], a1);                            \
            a2 = ffma2(qp[j + 2], Erp[j + 2], a2);                            \
            a3 = ffma2(qp[j + 3], Erp[j + 3], a3);                            \
        }                                                                     \
        u64 s = fadd2(fadd2(a0, a1), fadd2(a2, a3));                          \
        float qn = efp * (lo2(s) + hi2(s));                                   \
        const bool on = mk[i] > 0.0f;    /* warp-uniform */                   \
        qcur = on ? qn : qcur;                                                \
        pend = on ? 1.0f : pend;         /* consumed iff applied */           \
        sq[buf][lane] = qcur;                                                 \
        __syncthreads();                 /* 32-thr block: BAR floor ~3cyc */  \
        {                                                                     \
            const ulonglong2* p = (const ulonglong2*)sq[buf];                 \
            _Pragma("unroll")                                                 \
            for (int j = 0; j < 8; j++) {                                     \
                ulonglong2 v = p[j];                                          \
                qp[2 * j] = v.x;  qp[2 * j + 1] = v.y;                        \
            }                                                                 \
        }                                                                     \
        buf ^= 1;                                                             \
        if ((i & 3) == 3) {              /* exact power-of-2 rescale:   */    \
            int e = (int)(((unsigned)qp[0] >> 23) & 0xff);                    \
            off_e += (long long)(e - 127);                                    \
            pend *= __int_as_float((unsigned)(254 - e) << 23); /* 2^(127-e)*/ \
        }                                                                     \
    }                                                                         \
} while (0)

__global__ void __launch_bounds__(32) crf_fwd_kernel(
    const float* __restrict__ efeats,
    const float* __restrict__ mask,
    const int*   __restrict__ tgt,
    const float* __restrict__ transitions,
    float* __restrict__ out)
{
    __shared__ __align__(16) float sq[2][TT];   // ping-pong broadcast buffers
    __shared__ float tr[TT * TT];
    const int lane = threadIdx.x;
    const int b = blockIdx.x;

    #pragma unroll
    for (int i = lane; i < TT * TT; i += 32) tr[i] = transitions[i];
    __syncthreads();

    // packed E row for my 'next' tag
    u64 Erp[16];
    #pragma unroll
    for (int j = 0; j < 16; j++)
        Erp[j] = pack2(__expf(tr[lane * TT + 2 * j]), __expf(tr[lane * TT + 2 * j + 1]));

    // full q vector per lane; init = unit vector at START_IDX(=0)
    u64 qp[16];
    #pragma unroll
    for (int j = 0; j < 16; j++) qp[j] = 0ull;
    qp[0] = pack2(1.0f, 0.0f);
    float qcur = (lane == START_IDX) ? 1.0f : 0.0f;

    const float* fb  = efeats + (size_t)b * LL * TT;
    const float* mbp = mask   + (size_t)b * LL;
    const int*   tbp = tgt    + (size_t)b * LL;

    long long off_e = 0;     // claimed exponent offset
    float pend = 1.0f;       // pending exact power-of-2 factor
    int   buf  = 0;

    // double-buffered prefetch state
    float  f0[8], f1[8];
    float4 m0a, m0b, m1a, m1b;

    LOADG(f0, m0a, m0b, 0);                 // prime buffer 0

    for (int l0 = 0; l0 < LL; l0 += 16) {
        LOADG(f1, m1a, m1b, l0 + 8);        // prefetch next group
        PROC (f0, m0a, m0b);
        const int ln = (l0 + 16 < LL) ? (l0 + 16) : l0;  // last iter: dummy reload
        LOADG(f0, m0a, m0b, ln);
        PROC (f1, m1a, m1b);
    }

    // terminal logsumexp — every lane holds the full q vector (no reduction)
    float t = 0.0f;
    #pragma unroll
    for (int j = 0; j < 16; j++) {
        t += lo2(qp[j]) * __expf(tr[STOP_IDX * TT + 2 * j]);
        t += hi2(qp[j]) * __expf(tr[STOP_IDX * TT + 2 * j + 1]);
    }
    const int pend_e = (int)((__float_as_uint(pend) >> 23) & 0xff) - 127;

    // ---- gold score: lane-parallel over sequence positions ----
    float gt = 0.0f, ge = 0.0f;
    int   cnt = 0;
    #pragma unroll 8
    for (int base = 0; base < LL; base += 32) {
        const int l   = base + lane;
        const int tag = tbp[l];
        const int prv = (l > 0) ? tbp[l - 1] : START_IDX;
        const bool on = mbp[l] > 0.0f;
        const float onf = on ? 1.0f : 0.0f;
        gt = fmaf(onf, tr[tag * TT + prv], gt);
        ge = fmaf(onf, fb[(size_t)l * TT + tag], ge);
        cnt += on ? 1 : 0;
    }
    #pragma unroll
    for (int o = 16; o; o >>= 1) {
        gt  += __shfl_xor_sync(0xffffffffu, gt, o);
        ge  += __shfl_xor_sync(0xffffffffu, ge, o);
        cnt += __shfl_xor_sync(0xffffffffu, cnt, o);
    }

    if (lane == 0) {
        double fwd  = (double)(off_e + pend_e) * 0.6931471805599453 + (double)logf(t);
        int last = (cnt == 0) ? START_IDX : tbp[cnt - 1];
        double gold = (double)gt + (double)ge + (double)tr[STOP_IDX * TT + last];
        atomicAdd(out, (float)((fwd - gold) / (double)BB));
    }
}

extern "C" void kernel_launch(void* const* d_in, const int* in_sizes, int n_in,
                              void* d_out, int out_size)
{
    const float* efeats      = (const float*)d_in[0];
    const float* mask        = (const float*)d_in[1];
    const int*   tgt         = (const int*)  d_in[2];
    const float* transitions = (const float*)d_in[3];
    float* out = (float*)d_out;

    init_out_kernel<<<1, 1>>>(out);
    crf_fwd_kernel<<<BB, 32>>>(efeats, mask, tgt, transitions, out);
}

// round 11
// speedup vs baseline: 1.0004x; 1.0004x over previous
#include <cuda_runtime.h>
#include <cuda_bf16.h>

// CRF loss: scaled linear-domain forward scan + lane-parallel gold epilogue.
// 1 warp (=1 block, BAR.SYNC floor 3cyc) per batch element; lane = tag.
// Each lane holds the FULL q vector (16 packed f32x2 regs) + its packed
// exp-transition row: per-step matvec = 16 fma.rn.f32x2, zero shuffles.
// q broadcast via ping-pong smem: 1 STS + BAR + 8 broadcast LDS.128.
// Inner loop is minimal: no gold path (moved to vectorized epilogue), and
// rescaling is a pending power-of-2 factor folded into the next exp(feat)
// (1 FMUL) instead of 16 vector muls. Double-buffered global prefetch.

#define BB 256
#define LL 2048
#define TT 32
#define START_IDX 0
#define STOP_IDX 1

typedef unsigned long long u64;

__device__ __forceinline__ u64 ffma2(u64 a, u64 b, u64 c) {
    u64 d; asm("fma.rn.f32x2 %0, %1, %2, %3;" : "=l"(d) : "l"(a), "l"(b), "l"(c)); return d;
}
__device__ __forceinline__ u64 fadd2(u64 a, u64 b) {
    u64 d; asm("add.rn.f32x2 %0, %1, %2;" : "=l"(d) : "l"(a), "l"(b)); return d;
}
__device__ __forceinline__ u64 pack2(float lo, float hi) {
    return ((u64)__float_as_uint(hi) << 32) | (u64)__float_as_uint(lo);
}
__device__ __forceinline__ float lo2(u64 v) { return __uint_as_float((unsigned)v); }
__device__ __forceinline__ float hi2(u64 v) { return __uint_as_float((unsigned)(v >> 32)); }

__global__ void init_out_kernel(float* __restrict__ out) { *out = 0.0f; }

// issue 8 steps of loads (no consumption here -> latency hidden)
#define LOADG(F, MA, MB4, BASE) do {                                          \
    _Pragma("unroll")                                                         \
    for (int _i = 0; _i < 8; _i++)                                            \
        F[_i] = fb[(size_t)((BASE) + _i) * TT + lane];                        \
    MA  = *(const float4*)(mbp + (BASE));                                     \
    MB4 = *(const float4*)(mbp + (BASE) + 4);                                 \
} while (0)

// process 8 steps from a prefetched buffer (fully branch-free, no gold path)
#define PROC(F, MA, MB4) do {                                                 \
    float mk[8] = {MA.x, MA.y, MA.z, MA.w, MB4.x, MB4.y, MB4.z, MB4.w};       \
    _Pragma("unroll")                                                         \
    for (int i = 0; i < 8; i++) {                                             \
        float efp = __expf(F[i]) * pend;  /* pending rescale folded here */   \
        u64 a0 = 0ull, a1 = 0ull, a2 = 0ull, a3 = 0ull;                       \
        _Pragma("unroll")                                                     \
        for (int j = 0; j < 16; j += 4) { /* chains spread over LDS order */  \
            a0 = ffma2(qp[j + 0], Erp[j + 0], a0);                            \
            a1 = ffma2(qp[j + 1], Erp[j + 1], a1);                            \
            a2 = ffma2(qp[j + 2], Erp[j + 2], a2);                            \
            a3 = ffma2(qp[j + 3], Erp[j + 3], a3);                            \
        }                                                                     \
        u64 s = fadd2(fadd2(a0, a1), fadd2(a2, a3));                          \
        float qn = efp * (lo2(s) + hi2(s));                                   \
        const bool on = mk[i] > 0.0f;    /* warp-uniform */                   \
        qcur = on ? qn : qcur;                                                \
        pend = on ? 1.0f : pend;         /* consumed iff applied */           \
        sq[buf][lane] = qcur;                                                 \
        __syncthreads();                 /* 32-thr block: BAR floor ~3cyc */  \
        {                                                                     \
            const ulonglong2* p = (const ulonglong2*)sq[buf];                 \
            _Pragma("unroll")                                                 \
            for (int j = 0; j < 8; j++) {                                     \
                ulonglong2 v = p[j];                                          \
                qp[2 * j] = v.x;  qp[2 * j + 1] = v.y;                        \
            }                                                                 \
        }                                                                     \
        buf ^= 1;                                                             \
        if ((i & 3) == 3) {              /* exact power-of-2 rescale:   */    \
            int e = (int)(((unsigned)qp[0] >> 23) & 0xff);                    \
            off_e += (long long)(e - 127);                                    \
            pend *= __int_as_float((unsigned)(254 - e) << 23); /* 2^(127-e)*/ \
        }                                                                     \
    }                                                                         \
} while (0)

__global__ void __launch_bounds__(32) crf_fwd_kernel(
    const float* __restrict__ efeats,
    const float* __restrict__ mask,
    const int*   __restrict__ tgt,
    const float* __restrict__ transitions,
    float* __restrict__ out)
{
    __shared__ __align__(16) float sq[2][TT];   // ping-pong broadcast buffers
    __shared__ float tr[TT * TT];
    const int lane = threadIdx.x;
    const int b = blockIdx.x;

    #pragma unroll
    for (int i = lane; i < TT * TT; i += 32) tr[i] = transitions[i];
    __syncthreads();

    // packed E row for my 'next' tag
    u64 Erp[16];
    #pragma unroll
    for (int j = 0; j < 16; j++)
        Erp[j] = pack2(__expf(tr[lane * TT + 2 * j]), __expf(tr[lane * TT + 2 * j + 1]));

    // full q vector per lane; init = unit vector at START_IDX(=0)
    u64 qp[16];
    #pragma unroll
    for (int j = 0; j < 16; j++) qp[j] = 0ull;
    qp[0] = pack2(1.0f, 0.0f);
    float qcur = (lane == START_IDX) ? 1.0f : 0.0f;

    const float* fb  = efeats + (size_t)b * LL * TT;
    const float* mbp = mask   + (size_t)b * LL;
    const int*   tbp = tgt    + (size_t)b * LL;

    long long off_e = 0;     // claimed exponent offset
    float pend = 1.0f;       // pending exact power-of-2 factor
    int   buf  = 0;

    // double-buffered prefetch state
    float  f0[8], f1[8];
    float4 m0a, m0b, m1a, m1b;

    LOADG(f0, m0a, m0b, 0);                 // prime buffer 0

    for (int l0 = 0; l0 < LL; l0 += 16) {
        LOADG(f1, m1a, m1b, l0 + 8);        // prefetch next group
        PROC (f0, m0a, m0b);
        const int ln = (l0 + 16 < LL) ? (l0 + 16) : l0;  // last iter: dummy reload
        LOADG(f0, m0a, m0b, ln);
        PROC (f1, m1a, m1b);
    }

    // terminal logsumexp — every lane holds the full q vector (no reduction)
    float t = 0.0f;
    #pragma unroll
    for (int j = 0; j < 16; j++) {
        t += lo2(qp[j]) * __expf(tr[STOP_IDX * TT + 2 * j]);
        t += hi2(qp[j]) * __expf(tr[STOP_IDX * TT + 2 * j + 1]);
    }
    const int pend_e = (int)((__float_as_uint(pend) >> 23) & 0xff) - 127;

    // ---- gold score: lane-parallel over sequence positions ----
    float gt = 0.0f, ge = 0.0f;
    int   cnt = 0;
    #pragma unroll 8
    for (int base = 0; base < LL; base += 32) {
        const int l   = base + lane;
        const int tag = tbp[l];
        const int prv = (l > 0) ? tbp[l - 1] : START_IDX;
        const bool on = mbp[l] > 0.0f;
        const float onf = on ? 1.0f : 0.0f;
        gt = fmaf(onf, tr[tag * TT + prv], gt);
        ge = fmaf(onf, fb[(size_t)l * TT + tag], ge);
        cnt += on ? 1 : 0;
    }
    #pragma unroll
    for (int o = 16; o; o >>= 1) {
        gt  += __shfl_xor_sync(0xffffffffu, gt, o);
        ge  += __shfl_xor_sync(0xffffffffu, ge, o);
        cnt += __shfl_xor_sync(0xffffffffu, cnt, o);
    }

    if (lane == 0) {
        double fwd  = (double)(off_e + pend_e) * 0.6931471805599453 + (double)logf(t);
        int last = (cnt == 0) ? START_IDX : tbp[cnt - 1];
        double gold = (double)gt + (double)ge + (double)tr[STOP_IDX * TT + last];
        atomicAdd(out, (float)((fwd - gold) / (double)BB));
    }
}

extern "C" void kernel_launch(void* const* d_in, const int* in_sizes, int n_in,
                              void* d_out, int out_size)
{
    const float* efeats      = (const float*)d_in[0];
    const float* mask        = (const float*)d_in[1];
    const int*   tgt         = (const int*)  d_in[2];
    const float* transitions = (const float*)d_in[3];
    float* out = (float*)d_out;

    init_out_kernel<<<1, 1>>>(out);
    crf_fwd_kernel<<<BB, 32>>>(efeats, mask, tgt, transitions, out);
}